// round 1
// baseline (speedup 1.0000x reference)
#include <cuda_runtime.h>
#include <math.h>

// Problem: HybridQuanvolutionClassifier
// B=1024, NP=196 (14x14 patches), KP=4, 10 classes.
// One CTA per batch element, 320 threads (10 warps).

#define B_    1024
#define NP_   196
#define KP_   4
#define NC_   10
#define FEAT_ (NP_ * KP_)   // 784
#define THREADS_ 320

__global__ __launch_bounds__(THREADS_)
void hq_kernel(const float* __restrict__ x,      // [1024,1,28,28] = 1024*784
               const float* __restrict__ phi,    // [1024,196,4]
               const float* __restrict__ Wlin,   // [10,784]
               const float* __restrict__ blin,   // [10]
               float* __restrict__ out)          // [1024,10]
{
    const int b = blockIdx.x;
    const int t = threadIdx.x;

    __shared__ float sE[NP_][KP_];   // expvals
    __shared__ float sN[NP_][KP_];   // normalized states
    __shared__ float sF[FEAT_];      // smoothed feats
    __shared__ float sL[NC_];        // logits
    __shared__ float sLse;

    // -------- Phase 1: patch angles -> expvals (cumprod) + normalized states
    if (t < NP_) {
        const int hp = t / 14;
        const int wp = t - hp * 14;
        const float* xb = x + b * 784;
        const int r0 = (hp * 2) * 28 + wp * 2;
        const int r1 = r0 + 28;
        // flatten order (kh, kw): [ (0,0), (0,1), (1,0), (1,1) ]
        float th0 = xb[r0];
        float th1 = xb[r0 + 1];
        float th2 = xb[r1];
        float th3 = xb[r1 + 1];

        float4 ph = *reinterpret_cast<const float4*>(phi + ((size_t)b * NP_ + t) * KP_);

        float z0 = cosf(th0) * cosf(ph.x);
        float z1 = cosf(th1) * cosf(ph.y);
        float z2 = cosf(th2) * cosf(ph.z);
        float z3 = cosf(th3) * cosf(ph.w);

        float e0 = z0;
        float e1 = e0 * z1;
        float e2 = e1 * z2;
        float e3 = e2 * z3;

        sE[t][0] = e0; sE[t][1] = e1; sE[t][2] = e2; sE[t][3] = e3;

        float ss  = e0 * e0 + e1 * e1 + e2 * e2 + e3 * e3;
        float inv = 1.0f / (sqrtf(ss) + 1e-12f);
        sN[t][0] = e0 * inv; sN[t][1] = e1 * inv;
        sN[t][2] = e2 * inv; sN[t][3] = e3 * inv;
    }
    __syncthreads();

    // -------- Phase 2: per-row graph weights + Laplacian smoothing
    if (t < NP_) {
        const float n0 = sN[t][0], n1 = sN[t][1], n2 = sN[t][2], n3 = sN[t][3];
        float deg = 0.0f;
        float a0 = 0.0f, a1 = 0.0f, a2 = 0.0f, a3 = 0.0f;

        #pragma unroll 4
        for (int m = 0; m < NP_; m++) {
            float d = n0 * sN[m][0] + n1 * sN[m][1] + n2 * sN[m][2] + n3 * sN[m][3];
            float fid = d * d;
            float w = (fid >= 0.8f) ? 1.0f : ((fid >= 0.5f) ? 0.5f : 0.0f);
            w = (m == t) ? 0.0f : w;   // no self-edges
            deg += w;
            a0 = fmaf(w, sE[m][0], a0);
            a1 = fmaf(w, sE[m][1], a1);
            a2 = fmaf(w, sE[m][2], a2);
            a3 = fmaf(w, sE[m][3], a3);
        }
        // smoothed = (1 + deg) * E[t] - sum_m w*E[m]
        const float c = 1.0f + deg;
        sF[t * 4 + 0] = c * sE[t][0] - a0;
        sF[t * 4 + 1] = c * sE[t][1] - a1;
        sF[t * 4 + 2] = c * sE[t][2] - a2;
        sF[t * 4 + 3] = c * sE[t][3] - a3;
    }
    __syncthreads();

    // -------- Phase 3: logits = feats @ W^T + b  (warp w computes logit w)
    const int w = t >> 5;
    const int lane = t & 31;
    if (w < NC_) {
        const float* Wr = Wlin + (size_t)w * FEAT_;
        float acc = 0.0f;
        #pragma unroll
        for (int k = lane; k < FEAT_; k += 32)
            acc = fmaf(sF[k], Wr[k], acc);
        #pragma unroll
        for (int o = 16; o > 0; o >>= 1)
            acc += __shfl_down_sync(0xffffffffu, acc, o);
        if (lane == 0) sL[w] = acc + blin[w];
    }
    __syncthreads();

    // -------- log_softmax over 10 classes
    if (t == 0) {
        float mx = sL[0];
        #pragma unroll
        for (int c = 1; c < NC_; c++) mx = fmaxf(mx, sL[c]);
        float s = 0.0f;
        #pragma unroll
        for (int c = 0; c < NC_; c++) s += expf(sL[c] - mx);
        sLse = mx + logf(s);
    }
    __syncthreads();
    if (t < NC_) out[(size_t)b * NC_ + t] = sL[t] - sLse;
}

extern "C" void kernel_launch(void* const* d_in, const int* in_sizes, int n_in,
                              void* d_out, int out_size)
{
    const float* x    = (const float*)d_in[0];
    const float* phi  = (const float*)d_in[1];
    const float* Wlin = (const float*)d_in[2];
    const float* blin = (const float*)d_in[3];
    float* out = (float*)d_out;

    hq_kernel<<<B_, THREADS_>>>(x, phi, Wlin, blin, out);
}

// round 2
// speedup vs baseline: 1.1401x; 1.1401x over previous
#include <cuda_runtime.h>
#include <math.h>

// HybridQuanvolutionClassifier — B=1024, NP=196, KP=4, 10 classes.
// One CTA per batch element, 320 threads (10 warps). Issue-bound kernel:
// phase-2 inner loop minimized to ~15 instructions via float4 LDS + algebraic
// self-edge cancellation.

#define B_    1024
#define NP_   196
#define NC_   10
#define FEAT_ 784
#define THREADS_ 320

__global__ __launch_bounds__(THREADS_)
void hq_kernel(const float* __restrict__ x,      // [1024,1,28,28]
               const float* __restrict__ phi,    // [1024,196,4]
               const float* __restrict__ Wlin,   // [10,784]
               const float* __restrict__ blin,   // [10]
               float* __restrict__ out)          // [1024,10]
{
    const int b = blockIdx.x;
    const int t = threadIdx.x;

    __shared__ float4 sN4[NP_];   // normalized states
    __shared__ float4 sE4[NP_];   // expvals
    __shared__ float4 sF4[NP_];   // smoothed feats (patch-major = feat order)
    __shared__ float  sL[NC_];
    __shared__ float  sLse;

    // -------- Phase 1: angles -> expvals (cumprod) + normalized states
    if (t < NP_) {
        const int hp = t / 14;
        const int wp = t - hp * 14;
        const float* xb = x + b * 784;
        const int r0 = (hp * 2) * 28 + wp * 2;
        float th0 = xb[r0];
        float th1 = xb[r0 + 1];
        float th2 = xb[r0 + 28];
        float th3 = xb[r0 + 29];

        float4 ph = ((const float4*)phi)[b * NP_ + t];

        float e0 = cosf(th0) * cosf(ph.x);
        float e1 = e0 * (cosf(th1) * cosf(ph.y));
        float e2 = e1 * (cosf(th2) * cosf(ph.z));
        float e3 = e2 * (cosf(th3) * cosf(ph.w));
        sE4[t] = make_float4(e0, e1, e2, e3);

        float ss  = e0 * e0 + e1 * e1 + e2 * e2 + e3 * e3;
        float inv = 1.0f / (sqrtf(ss) + 1e-12f);
        sN4[t] = make_float4(e0 * inv, e1 * inv, e2 * inv, e3 * inv);
    }
    __syncthreads();

    // -------- Phase 2: graph weights + Laplacian smoothing (row per thread)
    // Self-edge needs NO special handling: it adds w_tt*E_t to the degree term
    // and w_tt*E_t to the weighted sum, which cancel in (1+deg)*E_t - a.
    if (t < NP_) {
        const float4 nt = sN4[t];
        float deg = 0.0f;
        float a0 = 0.0f, a1 = 0.0f, a2 = 0.0f, a3 = 0.0f;

        #pragma unroll 4
        for (int m = 0; m < NP_; m++) {
            float4 nm = sN4[m];
            float4 em = sE4[m];
            float d = nt.x * nm.x;
            d = fmaf(nt.y, nm.y, d);
            d = fmaf(nt.z, nm.z, d);
            d = fmaf(nt.w, nm.w, d);
            float fid = d * d;
            float w = (fid >= 0.8f ? 0.5f : 0.0f) + (fid >= 0.5f ? 0.5f : 0.0f);
            deg += w;
            a0 = fmaf(w, em.x, a0);
            a1 = fmaf(w, em.y, a1);
            a2 = fmaf(w, em.z, a2);
            a3 = fmaf(w, em.w, a3);
        }

        const float4 et = sE4[t];
        const float c = 1.0f + deg;
        sF4[t] = make_float4(fmaf(c, et.x, -a0), fmaf(c, et.y, -a1),
                             fmaf(c, et.z, -a2), fmaf(c, et.w, -a3));
    }
    __syncthreads();

    // -------- Phase 3: logits = feats @ W^T + b  (warp w -> logit w), float4
    const int wi   = t >> 5;
    const int lane = t & 31;
    if (wi < NC_) {
        const float4* Wr = (const float4*)(Wlin + (size_t)wi * FEAT_);
        float acc = 0.0f;
        #pragma unroll
        for (int k = lane; k < NP_; k += 32) {
            float4 wv = Wr[k];
            float4 fv = sF4[k];
            acc = fmaf(wv.x, fv.x, acc);
            acc = fmaf(wv.y, fv.y, acc);
            acc = fmaf(wv.z, fv.z, acc);
            acc = fmaf(wv.w, fv.w, acc);
        }
        #pragma unroll
        for (int o = 16; o > 0; o >>= 1)
            acc += __shfl_down_sync(0xffffffffu, acc, o);
        if (lane == 0) sL[wi] = acc + blin[wi];
    }
    __syncthreads();

    // -------- log_softmax over 10 classes
    if (t == 0) {
        float mx = sL[0];
        #pragma unroll
        for (int c = 1; c < NC_; c++) mx = fmaxf(mx, sL[c]);
        float s = 0.0f;
        #pragma unroll
        for (int c = 0; c < NC_; c++) s += expf(sL[c] - mx);
        sLse = mx + logf(s);
    }
    __syncthreads();
    if (t < NC_) out[(size_t)b * NC_ + t] = sL[t] - sLse;
}

extern "C" void kernel_launch(void* const* d_in, const int* in_sizes, int n_in,
                              void* d_out, int out_size)
{
    const float* x    = (const float*)d_in[0];
    const float* phi  = (const float*)d_in[1];
    const float* Wlin = (const float*)d_in[2];
    const float* blin = (const float*)d_in[3];
    float* out = (float*)d_out;

    hq_kernel<<<B_, THREADS_>>>(x, phi, Wlin, blin, out);
}

// round 4
// speedup vs baseline: 1.2382x; 1.0861x over previous
#include <cuda_runtime.h>
#include <math.h>

// HybridQuanvolutionClassifier — B=1024, NP=196, KP=4, 10 classes.
// One CTA per batch element, 224 threads (7 warps): at 32 regs/thread this
// gives 9 CTAs/SM -> 148*9 = 1332 >= 1024 CTAs resident in a SINGLE wave
// (the 320-thread version had a 136-CTA tail wave).

#define B_    1024
#define NP_   196
#define NC_   10
#define FEAT_ 784
#define THREADS_ 224

__global__ __launch_bounds__(THREADS_)
void hq_kernel(const float* __restrict__ x,      // [1024,1,28,28]
               const float* __restrict__ phi,    // [1024,196,4]
               const float* __restrict__ Wlin,   // [10,784]
               const float* __restrict__ blin,   // [10]
               float* __restrict__ out)          // [1024,10]
{
    const int b = blockIdx.x;
    const int t = threadIdx.x;

    __shared__ float4 sN4[NP_];   // normalized states
    __shared__ float4 sE4[NP_];   // expvals
    __shared__ float4 sF4[NP_];   // smoothed feats (patch-major = feat order)
    __shared__ float  sL[NC_];
    __shared__ float  sLse;

    // -------- Phase 1: angles -> expvals (cumprod) + normalized states
    float4 myE, myN;
    if (t < NP_) {
        const int hp = t / 14;
        const int wp = t - hp * 14;
        const float* xb = x + b * 784;
        const int r0 = (hp * 2) * 28 + wp * 2;
        float th0 = xb[r0];
        float th1 = xb[r0 + 1];
        float th2 = xb[r0 + 28];
        float th3 = xb[r0 + 29];

        float4 ph = ((const float4*)phi)[b * NP_ + t];

        float e0 = cosf(th0) * cosf(ph.x);
        float e1 = e0 * (cosf(th1) * cosf(ph.y));
        float e2 = e1 * (cosf(th2) * cosf(ph.z));
        float e3 = e2 * (cosf(th3) * cosf(ph.w));
        myE = make_float4(e0, e1, e2, e3);
        sE4[t] = myE;

        float ss  = e0 * e0 + e1 * e1 + e2 * e2 + e3 * e3;
        float inv = 1.0f / (sqrtf(ss) + 1e-12f);
        myN = make_float4(e0 * inv, e1 * inv, e2 * inv, e3 * inv);
        sN4[t] = myN;
    }
    __syncthreads();

    // -------- Phase 2: graph weights + Laplacian smoothing (row per thread)
    // Self-edge cancels algebraically in (1+deg)*E_t - a, so no m==t branch.
    if (t < NP_) {
        const float4 nt = myN;
        float deg = 0.0f;
        float a0 = 0.0f, a1 = 0.0f, a2 = 0.0f, a3 = 0.0f;

        #pragma unroll 7
        for (int m = 0; m < NP_; m++) {
            float4 nm = sN4[m];
            float4 em = sE4[m];
            float d = nt.x * nm.x;
            d = fmaf(nt.y, nm.y, d);
            d = fmaf(nt.z, nm.z, d);
            d = fmaf(nt.w, nm.w, d);
            float fid = d * d;
            float w = (fid >= 0.8f ? 0.5f : 0.0f) + (fid >= 0.5f ? 0.5f : 0.0f);
            deg += w;
            a0 = fmaf(w, em.x, a0);
            a1 = fmaf(w, em.y, a1);
            a2 = fmaf(w, em.z, a2);
            a3 = fmaf(w, em.w, a3);
        }

        const float4 et = myE;
        const float c = 1.0f + deg;
        sF4[t] = make_float4(fmaf(c, et.x, -a0), fmaf(c, et.y, -a1),
                             fmaf(c, et.z, -a2), fmaf(c, et.w, -a3));
    }
    __syncthreads();

    // -------- Phase 3: logits = feats @ W^T + b (7 warps cover 10 logits)
    const int wi   = t >> 5;
    const int lane = t & 31;
    for (int li = wi; li < NC_; li += 7) {
        const float4* Wr = (const float4*)(Wlin + (size_t)li * FEAT_);
        float acc = 0.0f;
        #pragma unroll
        for (int k = lane; k < NP_; k += 32) {
            float4 wv = Wr[k];
            float4 fv = sF4[k];
            acc = fmaf(wv.x, fv.x, acc);
            acc = fmaf(wv.y, fv.y, acc);
            acc = fmaf(wv.z, fv.z, acc);
            acc = fmaf(wv.w, fv.w, acc);
        }
        #pragma unroll
        for (int o = 16; o > 0; o >>= 1)
            acc += __shfl_down_sync(0xffffffffu, acc, o);
        if (lane == 0) sL[li] = acc + blin[li];
    }
    __syncthreads();

    // -------- log_softmax over 10 classes
    if (t == 0) {
        float mx = sL[0];
        #pragma unroll
        for (int c = 1; c < NC_; c++) mx = fmaxf(mx, sL[c]);
        float s = 0.0f;
        #pragma unroll
        for (int c = 0; c < NC_; c++) s += expf(sL[c] - mx);
        sLse = mx + logf(s);
    }
    __syncthreads();
    if (t < NC_) out[(size_t)b * NC_ + t] = sL[t] - sLse;
}

extern "C" void kernel_launch(void* const* d_in, const int* in_sizes, int n_in,
                              void* d_out, int out_size)
{
    const float* x    = (const float*)d_in[0];
    const float* phi  = (const float*)d_in[1];
    const float* Wlin = (const float*)d_in[2];
    const float* blin = (const float*)d_in[3];
    float* out = (float*)d_out;

    hq_kernel<<<B_, THREADS_>>>(x, phi, Wlin, blin, out);
}